// round 1
// baseline (speedup 1.0000x reference)
#include <cuda_runtime.h>
#include <math.h>

#define NTOK 4096      // B*T
#define EDIM 1024
#define HID  4096
#define NLAYER 12
#define NHEAD 16
#define HDIM 64
#define BATCH 2048
#define VOC  32000

// -------- scratch (device globals; no allocation allowed) --------
__device__ float g_X [NTOK * EDIM];
__device__ float g_X2[NTOK * EDIM];
__device__ float g_Q [NTOK * EDIM];
__device__ float g_K [NTOK * EDIM];
__device__ float g_V [NTOK * EDIM];
__device__ float g_O [NTOK * EDIM];
__device__ float g_H1[NTOK * HID];

// -------- embedding: x[i,:] = emb[tokens[i],:] + pos[i%2,:] --------
__global__ void embed_kernel(const int* __restrict__ tokens,
                             const float* __restrict__ emb,
                             const float* __restrict__ pos,
                             float* __restrict__ X)
{
    int idx = blockIdx.x * blockDim.x + threadIdx.x;   // over NTOK*EDIM/4
    int i  = idx / (EDIM / 4);
    int e4 = idx % (EDIM / 4);
    int tok = tokens[i];
    float4 a = ((const float4*)(emb + (size_t)tok * EDIM))[e4];
    float4 p = ((const float4*)(pos + (size_t)(i & 1) * EDIM))[e4];
    float4 r;
    r.x = a.x + p.x; r.y = a.y + p.y; r.z = a.z + p.z; r.w = a.w + p.w;
    ((float4*)(X + (size_t)i * EDIM))[e4] = r;
}

// -------- generic SGEMM: C = f(A[M,K] @ B[K,N] + bias) + res --------
// HEADED: B is laid out (NHEAD, K, 64) — per-head (K x 64) row-major blocks,
//         effective column c maps to head c>>6, inner col c&63.
// Epilogue order matches the reference: +bias, relu, +residual.
template<bool HEADED, bool RELU, bool HAS_BIAS, bool HAS_RES>
__global__ void __launch_bounds__(256)
gemm_kernel(const float* __restrict__ A, int lda,
            const float* __restrict__ Bm,
            const float* __restrict__ bias,
            const float* __restrict__ res,
            float* __restrict__ C,
            int M, int N, int K)
{
    __shared__ float As[8][128];
    __shared__ float Bs[8][128];

    const int tid = threadIdx.x;
    const int rowBase = blockIdx.y * 128;
    const int colBase = blockIdx.x * 128;
    const int tx = tid & 15;        // 16 col groups of 8
    const int ty = tid >> 4;        // 16 row groups of 8

    float acc[8][8];
#pragma unroll
    for (int i = 0; i < 8; i++)
#pragma unroll
        for (int j = 0; j < 8; j++) acc[i][j] = 0.0f;

    // A tile loader: 128 rows x 8 k, float4 per thread
    const int aRow = tid >> 1;
    const int aCol = (tid & 1) * 4;
    const float* Aptr = A + (size_t)(rowBase + aRow) * lda + aCol;

    // B tile loader: 8 k-rows x 128 cols, float4 per thread
    const int bRow = tid >> 5;
    const int bCol = (tid & 31) * 4;
    const float* Bptr;
    int bstep;
    if (HEADED) {
        int c = colBase + bCol;
        Bptr  = Bm + (size_t)(c >> 6) * ((size_t)K * 64) + (size_t)bRow * 64 + (c & 63);
        bstep = 8 * 64;
    } else {
        Bptr  = Bm + (size_t)bRow * N + colBase + bCol;
        bstep = 8 * N;
    }

    for (int k0 = 0; k0 < K; k0 += 8) {
        float4 av = *(const float4*)Aptr;
        Aptr += 8;
        As[aCol + 0][aRow] = av.x;
        As[aCol + 1][aRow] = av.y;
        As[aCol + 2][aRow] = av.z;
        As[aCol + 3][aRow] = av.w;

        float4 bv = *(const float4*)Bptr;
        Bptr += bstep;
        *(float4*)&Bs[bRow][bCol] = bv;

        __syncthreads();

#pragma unroll
        for (int kk = 0; kk < 8; kk++) {
            float a[8], b[8];
            *(float4*)(a)     = *(const float4*)&As[kk][ty * 8];
            *(float4*)(a + 4) = *(const float4*)&As[kk][ty * 8 + 4];
            *(float4*)(b)     = *(const float4*)&Bs[kk][tx * 8];
            *(float4*)(b + 4) = *(const float4*)&Bs[kk][tx * 8 + 4];
#pragma unroll
            for (int i = 0; i < 8; i++)
#pragma unroll
                for (int j = 0; j < 8; j++)
                    acc[i][j] = fmaf(a[i], b[j], acc[i][j]);
        }
        __syncthreads();
    }

    // epilogue
    const int col0 = colBase + tx * 8;
    float bia[8];
    if (HAS_BIAS) {
        *(float4*)(bia)     = *(const float4*)(bias + col0);
        *(float4*)(bia + 4) = *(const float4*)(bias + col0 + 4);
    }
#pragma unroll
    for (int i = 0; i < 8; i++) {
        const int r = rowBase + ty * 8 + i;
        float* crow = C + (size_t)r * N + col0;
        float v[8];
#pragma unroll
        for (int j = 0; j < 8; j++) {
            float c = acc[i][j];
            if (HAS_BIAS) c += bia[j];
            if (RELU)     c = fmaxf(c, 0.0f);
            v[j] = c;
        }
        if (HAS_RES) {
            const float* rrow = res + (size_t)r * N + col0;
            float rr[8];
            *(float4*)(rr)     = *(const float4*)(rrow);
            *(float4*)(rr + 4) = *(const float4*)(rrow + 4);
#pragma unroll
            for (int j = 0; j < 8; j++) v[j] += rr[j];
        }
        *(float4*)(crow)     = *(const float4*)(v);
        *(float4*)(crow + 4) = *(const float4*)(v + 4);
    }
}

// -------- attention: per (b,h), T=2, softmax over 2 keys --------
__global__ void attn_kernel(const float* __restrict__ Q,
                            const float* __restrict__ Kt,
                            const float* __restrict__ Vt,
                            float* __restrict__ O)
{
    const int bh = blockIdx.x;            // b*NHEAD + h
    const int b = bh >> 4;
    const int h = bh & 15;
    const int o = threadIdx.x;            // 0..63
    const int col = h * HDIM + o;
    const size_t i0 = (size_t)(b * 2) * EDIM + col;
    const size_t i1 = i0 + EDIM;

    float q0 = Q[i0],  q1 = Q[i1];
    float k0 = Kt[i0], k1 = Kt[i1];
    float v0 = Vt[i0], v1 = Vt[i1];

    float d00 = q0 * k0, d01 = q0 * k1, d10 = q1 * k0, d11 = q1 * k1;

    const unsigned mask = 0xffffffffu;
#pragma unroll
    for (int off = 16; off; off >>= 1) {
        d00 += __shfl_down_sync(mask, d00, off);
        d01 += __shfl_down_sync(mask, d01, off);
        d10 += __shfl_down_sync(mask, d10, off);
        d11 += __shfl_down_sync(mask, d11, off);
    }

    __shared__ float part[4][2];
    __shared__ float p[4];
    const int warp = o >> 5;
    if ((o & 31) == 0) {
        part[0][warp] = d00; part[1][warp] = d01;
        part[2][warp] = d10; part[3][warp] = d11;
    }
    __syncthreads();
    if (o == 0) {
        const float scale = 0.125f;      // 1/sqrt(64)
        float s00 = (part[0][0] + part[0][1]) * scale;
        float s01 = (part[1][0] + part[1][1]) * scale;
        float s10 = (part[2][0] + part[2][1]) * scale;
        float s11 = (part[3][0] + part[3][1]) * scale;
        float m0 = fmaxf(s00, s01);
        float e00 = expf(s00 - m0), e01 = expf(s01 - m0);
        float inv0 = 1.0f / (e00 + e01);
        float m1 = fmaxf(s10, s11);
        float e10 = expf(s10 - m1), e11 = expf(s11 - m1);
        float inv1 = 1.0f / (e10 + e11);
        p[0] = e00 * inv0; p[1] = e01 * inv0;
        p[2] = e10 * inv1; p[3] = e11 * inv1;
    }
    __syncthreads();

    O[i0] = p[0] * v0 + p[1] * v1;
    O[i1] = p[2] * v0 + p[3] * v1;
}

// -------- launcher --------
extern "C" void kernel_launch(void* const* d_in, const int* in_sizes, int n_in,
                              void* d_out, int out_size)
{
    (void)in_sizes; (void)n_in; (void)out_size;
    const int*   tokens  = (const int*)  d_in[0];
    const float* emb     = (const float*)d_in[1];
    const float* pos     = (const float*)d_in[2];
    const float* Wq      = (const float*)d_in[3];
    const float* Wk      = (const float*)d_in[4];
    const float* Wv      = (const float*)d_in[5];
    const float* Wo      = (const float*)d_in[6];
    const float* W1      = (const float*)d_in[7];
    const float* b1      = (const float*)d_in[8];
    const float* W2      = (const float*)d_in[9];
    const float* b2      = (const float*)d_in[10];
    const float* unembed = (const float*)d_in[11];
    float* out = (float*)d_out;

    float *X, *X2, *Q, *K, *V, *O, *H1;
    cudaGetSymbolAddress((void**)&X,  g_X);
    cudaGetSymbolAddress((void**)&X2, g_X2);
    cudaGetSymbolAddress((void**)&Q,  g_Q);
    cudaGetSymbolAddress((void**)&K,  g_K);
    cudaGetSymbolAddress((void**)&V,  g_V);
    cudaGetSymbolAddress((void**)&O,  g_O);
    cudaGetSymbolAddress((void**)&H1, g_H1);

    embed_kernel<<<(NTOK * EDIM / 4) / 256, 256>>>(tokens, emb, pos, X);

    const dim3 blk(256);
    const dim3 gE (EDIM / 128, NTOK / 128);   // (8, 32)
    const dim3 gH (HID  / 128, NTOK / 128);   // (32, 32)

    for (int l = 0; l < NLAYER; l++) {
        const float* Wql = Wq + (size_t)l * NHEAD * EDIM * HDIM;
        const float* Wkl = Wk + (size_t)l * NHEAD * EDIM * HDIM;
        const float* Wvl = Wv + (size_t)l * NHEAD * EDIM * HDIM;
        const float* Wol = Wo + (size_t)l * EDIM * EDIM;
        const float* W1l = W1 + (size_t)l * EDIM * HID;
        const float* b1l = b1 + (size_t)l * HID;
        const float* W2l = W2 + (size_t)l * HID * EDIM;
        const float* b2l = b2 + (size_t)l * EDIM;

        gemm_kernel<true,  false, false, false><<<gE, blk>>>(X,  EDIM, Wql, nullptr, nullptr, Q,  NTOK, EDIM, EDIM);
        gemm_kernel<true,  false, false, false><<<gE, blk>>>(X,  EDIM, Wkl, nullptr, nullptr, K,  NTOK, EDIM, EDIM);
        gemm_kernel<true,  false, false, false><<<gE, blk>>>(X,  EDIM, Wvl, nullptr, nullptr, V,  NTOK, EDIM, EDIM);

        attn_kernel<<<BATCH * NHEAD, 64>>>(Q, K, V, O);

        // x2 = O @ Wo + x
        gemm_kernel<false, false, false, true ><<<gE, blk>>>(O,  EDIM, Wol, nullptr, X,  X2, NTOK, EDIM, EDIM);
        // h1 = relu(x2 @ W1 + b1)
        gemm_kernel<false, true,  true,  false><<<gH, blk>>>(X2, EDIM, W1l, b1l,    nullptr, H1, NTOK, HID,  EDIM);
        // x = relu(h1 @ W2 + b2) + x2
        gemm_kernel<false, true,  true,  true ><<<gE, blk>>>(H1, HID,  W2l, b2l,    X2, X,  NTOK, EDIM, HID);
    }

    // logits = x[:, -1, :] @ unembed   (odd token rows)
    const dim3 gF(VOC / 128, BATCH / 128);    // (250, 16)
    gemm_kernel<false, false, false, false><<<gF, blk>>>(X + EDIM, 2 * EDIM, unembed,
                                                         nullptr, nullptr, out,
                                                         BATCH, VOC, EDIM);
}

// round 2
// speedup vs baseline: 2.1963x; 2.1963x over previous
#include <cuda_runtime.h>
#include <cuda_bf16.h>
#include <cstdint>
#include <math.h>

#define NTOK 4096
#define EDIM 1024
#define HID  4096
#define NLAYER 12
#define NHEAD 16
#define HDIM 64
#define BATCH 2048
#define VOC  32000
#define QKVN 3072

typedef __nv_bfloat16 bf16;

// ---------------- scratch (device globals) ----------------
// weights: transposed [N,K], split into bf16 hi/lo planes
__device__ bf16 g_Wqkv_h[NLAYER * QKVN * EDIM];
__device__ bf16 g_Wqkv_l[NLAYER * QKVN * EDIM];
__device__ bf16 g_Wo_h [NLAYER * EDIM * EDIM];
__device__ bf16 g_Wo_l [NLAYER * EDIM * EDIM];
__device__ bf16 g_W1_h [NLAYER * HID * EDIM];
__device__ bf16 g_W1_l [NLAYER * HID * EDIM];
__device__ bf16 g_W2_h [NLAYER * EDIM * HID];
__device__ bf16 g_W2_l [NLAYER * EDIM * HID];
__device__ bf16 g_Ue_h [VOC * EDIM];
__device__ bf16 g_Ue_l [VOC * EDIM];
// activations
__device__ float g_X  [NTOK * EDIM];
__device__ float g_X2 [NTOK * EDIM];
__device__ bf16  g_Xh [NTOK * EDIM];
__device__ bf16  g_Xl [NTOK * EDIM];
__device__ bf16  g_X2h[NTOK * EDIM];
__device__ bf16  g_X2l[NTOK * EDIM];
__device__ float g_QKV[NTOK * QKVN];
__device__ bf16  g_Oh [NTOK * EDIM];
__device__ bf16  g_Ol [NTOK * EDIM];
__device__ bf16  g_H1h[NTOK * HID];
__device__ bf16  g_H1l[NTOK * HID];

__device__ __forceinline__ void split2(float v, bf16& h, bf16& l) {
    h = __float2bfloat16(v);
    l = __float2bfloat16(v - __bfloat162float(h));
}

// ---------------- weight transpose + split: src[K,N] -> dst[N,K] hi/lo ----------------
__global__ void tconv_kernel(const float* __restrict__ src,
                             bf16* __restrict__ dhi, bf16* __restrict__ dlo,
                             int K, int N)
{
    __shared__ float t[32][33];
    const int z = blockIdx.z;
    src += (size_t)z * K * N;
    dhi += (size_t)z * K * N;
    dlo += (size_t)z * K * N;
    const int k0 = blockIdx.y * 32, n0 = blockIdx.x * 32;
    const int tx = threadIdx.x, ty = threadIdx.y;
#pragma unroll
    for (int j = 0; j < 4; j++)
        t[ty + 8 * j][tx] = src[(size_t)(k0 + ty + 8 * j) * N + n0 + tx];
    __syncthreads();
#pragma unroll
    for (int j = 0; j < 4; j++) {
        float v = t[tx][ty + 8 * j];
        bf16 h, l; split2(v, h, l);
        size_t o = (size_t)(n0 + ty + 8 * j) * K + k0 + tx;
        dhi[o] = h; dlo[o] = l;
    }
}

// QKV gather + transpose + split.
// src Wq/Wk/Wv: (L, H, E, HD) row-major. dst per layer: [3072][1024] rows:
// n = which*1024 + h*64 + i, value = W[l][h][k][i].
__global__ void tconv_qkv_kernel(const float* __restrict__ Wq,
                                 const float* __restrict__ Wk,
                                 const float* __restrict__ Wv,
                                 bf16* __restrict__ dhi, bf16* __restrict__ dlo)
{
    __shared__ float t[32][33];
    const int z = blockIdx.z;          // l*48 + which*16 + h
    const int l = z / 48;
    const int rr = z % 48;
    const int which = rr / 16;
    const int h = rr % 16;
    const float* src = (which == 0 ? Wq : which == 1 ? Wk : Wv)
                       + ((size_t)(l * NHEAD + h) * EDIM) * HDIM;   // [k][i], 1024x64
    const int i0 = blockIdx.x * 32;    // 0 or 32
    const int k0 = blockIdx.y * 32;
    const int tx = threadIdx.x, ty = threadIdx.y;
#pragma unroll
    for (int j = 0; j < 4; j++)
        t[ty + 8 * j][tx] = src[(size_t)(k0 + ty + 8 * j) * HDIM + i0 + tx];
    __syncthreads();
    bf16* bh = dhi + (size_t)l * QKVN * EDIM;
    bf16* bl = dlo + (size_t)l * QKVN * EDIM;
#pragma unroll
    for (int j = 0; j < 4; j++) {
        float v = t[tx][ty + 8 * j];
        bf16 hh, ll; split2(v, hh, ll);
        int n = which * 1024 + h * 64 + i0 + ty + 8 * j;
        size_t o = (size_t)n * EDIM + k0 + tx;
        bh[o] = hh; bl[o] = ll;
    }
}

// ---------------- embedding ----------------
__global__ void embed_kernel(const int* __restrict__ tokens,
                             const float* __restrict__ emb,
                             const float* __restrict__ pos,
                             float* __restrict__ X,
                             bf16* __restrict__ Xh, bf16* __restrict__ Xl)
{
    int idx = blockIdx.x * blockDim.x + threadIdx.x;
    int i  = idx / (EDIM / 4);
    int e4 = idx % (EDIM / 4);
    int tok = tokens[i];
    float4 a = ((const float4*)(emb + (size_t)tok * EDIM))[e4];
    float4 p = ((const float4*)(pos + (size_t)(i & 1) * EDIM))[e4];
    float r[4] = { a.x + p.x, a.y + p.y, a.z + p.z, a.w + p.w };
    float4 rf; rf.x = r[0]; rf.y = r[1]; rf.z = r[2]; rf.w = r[3];
    ((float4*)(X + (size_t)i * EDIM))[e4] = rf;
    bf16 hh[4], ll[4];
#pragma unroll
    for (int j = 0; j < 4; j++) split2(r[j], hh[j], ll[j]);
    size_t o = (size_t)i * EDIM + e4 * 4;
#pragma unroll
    for (int j = 0; j < 4; j++) { Xh[o + j] = hh[j]; Xl[o + j] = ll[j]; }
}

// ---------------- attention (T=2) ----------------
__global__ void attn_kernel(const float* __restrict__ QKV,
                            bf16* __restrict__ Oh, bf16* __restrict__ Ol)
{
    const int bh = blockIdx.x;
    const int b = bh >> 4;
    const int h = bh & 15;
    const int o = threadIdx.x;                 // 0..63
    const size_t q0i = (size_t)(b * 2) * QKVN + h * HDIM + o;
    const size_t q1i = q0i + QKVN;

    float q0 = QKV[q0i],        q1 = QKV[q1i];
    float k0 = QKV[q0i + 1024], k1 = QKV[q1i + 1024];
    float v0 = QKV[q0i + 2048], v1 = QKV[q1i + 2048];

    float d00 = q0 * k0, d01 = q0 * k1, d10 = q1 * k0, d11 = q1 * k1;
    const unsigned mask = 0xffffffffu;
#pragma unroll
    for (int off = 16; off; off >>= 1) {
        d00 += __shfl_down_sync(mask, d00, off);
        d01 += __shfl_down_sync(mask, d01, off);
        d10 += __shfl_down_sync(mask, d10, off);
        d11 += __shfl_down_sync(mask, d11, off);
    }
    __shared__ float part[4][2];
    __shared__ float p[4];
    const int warp = o >> 5;
    if ((o & 31) == 0) {
        part[0][warp] = d00; part[1][warp] = d01;
        part[2][warp] = d10; part[3][warp] = d11;
    }
    __syncthreads();
    if (o == 0) {
        const float scale = 0.125f;
        float s00 = (part[0][0] + part[0][1]) * scale;
        float s01 = (part[1][0] + part[1][1]) * scale;
        float s10 = (part[2][0] + part[2][1]) * scale;
        float s11 = (part[3][0] + part[3][1]) * scale;
        float m0 = fmaxf(s00, s01);
        float e00 = expf(s00 - m0), e01 = expf(s01 - m0);
        float i0 = 1.0f / (e00 + e01);
        float m1 = fmaxf(s10, s11);
        float e10 = expf(s10 - m1), e11 = expf(s11 - m1);
        float i1 = 1.0f / (e10 + e11);
        p[0] = e00 * i0; p[1] = e01 * i0; p[2] = e10 * i1; p[3] = e11 * i1;
    }
    __syncthreads();
    const size_t o0 = (size_t)(b * 2) * EDIM + h * HDIM + o;
    bf16 hh, ll;
    split2(p[0] * v0 + p[1] * v1, hh, ll); Oh[o0] = hh;        Ol[o0] = ll;
    split2(p[2] * v0 + p[3] * v1, hh, ll); Oh[o0 + EDIM] = hh; Ol[o0 + EDIM] = ll;
}

// ---------------- 3xBF16 tensor-core GEMM ----------------
// C[M,N] = A[M,K] @ B[K,N],  A given as hi/lo planes [M,K] (row stride lda),
// B given transposed hi/lo planes [N,K] (row stride K).
#define MMA_BF16(d, a, b0, b1)                                             \
    asm volatile("mma.sync.aligned.m16n8k16.row.col.f32.bf16.bf16.f32 "    \
                 "{%0,%1,%2,%3},{%4,%5,%6,%7},{%8,%9},{%0,%1,%2,%3};"      \
                 : "+f"(d[0]), "+f"(d[1]), "+f"(d[2]), "+f"(d[3])          \
                 : "r"(a[0]), "r"(a[1]), "r"(a[2]), "r"(a[3]),             \
                   "r"(b0), "r"(b1))

__device__ __forceinline__ void cpa16(uint32_t dst, const void* src) {
    asm volatile("cp.async.cg.shared.global [%0], [%1], 16;\n" :: "r"(dst), "l"(src));
}

// smem layout per stage (bf16 halves): aH[128*24] aL[128*24] bH[128*24] bL[128*24]
// stage stride 24576 bytes; plane stride 6144 bytes; row stride 24 halves (48 B).
#define GSTAGE_B 24576
#define GPLANE_B 6144

template<bool BIAS, bool RELU, bool RES, bool WF32, bool WBF>
__global__ void __launch_bounds__(256, 2)
gemm3_kernel(const bf16* __restrict__ Ah_, const bf16* __restrict__ Al_, int lda,
             const bf16* __restrict__ Bh_, const bf16* __restrict__ Bl_,
             const float* __restrict__ bias, const float* __restrict__ resid,
             float* __restrict__ Cf, bf16* __restrict__ Ch, bf16* __restrict__ Cl,
             int N, int K)
{
    extern __shared__ bf16 smem[];
    const int tid  = threadIdx.x;
    const int lane = tid & 31, warp = tid >> 5;
    const int wm = warp >> 2, wn = warp & 3;       // 2x4 warp grid
    const int g = lane >> 2, t = lane & 3;
    const int rowBase = blockIdx.y * 128;
    const int colBase = blockIdx.x * 128;

    // loader assignment: r = row in tile (0..127), c = 0/8 halves within 16-wide row
    const int lr = tid >> 1;
    const int lc = (tid & 1) * 8;
    const bf16* gAh = Ah_ + (size_t)(rowBase + lr) * lda + lc;
    const bf16* gAl = Al_ + (size_t)(rowBase + lr) * lda + lc;
    const bf16* gBh = Bh_ + (size_t)(colBase + lr) * K + lc;
    const bf16* gBl = Bl_ + (size_t)(colBase + lr) * K + lc;
    const uint32_t sbase = (uint32_t)__cvta_generic_to_shared(smem);
    const uint32_t sw = sbase + (lr * 24 + lc) * 2;

#define LOAD_STAGE(S, KT)                                       \
    do {                                                        \
        uint32_t b_ = sw + (S) * GSTAGE_B;                      \
        int ko_ = (KT) * 16;                                    \
        cpa16(b_,                gAh + ko_);                    \
        cpa16(b_ + GPLANE_B,     gAl + ko_);                    \
        cpa16(b_ + 2 * GPLANE_B, gBh + ko_);                    \
        cpa16(b_ + 3 * GPLANE_B, gBl + ko_);                    \
    } while (0)

    float acc[4][4][4];
#pragma unroll
    for (int i = 0; i < 4; i++)
#pragma unroll
        for (int j = 0; j < 4; j++)
#pragma unroll
            for (int q = 0; q < 4; q++) acc[i][j][q] = 0.0f;

    const int KT = K >> 4;
    LOAD_STAGE(0, 0); asm volatile("cp.async.commit_group;");
    LOAD_STAGE(1, 1); asm volatile("cp.async.commit_group;");

    for (int kt = 0; kt < KT; ++kt) {
        asm volatile("cp.async.wait_group 1;" ::: "memory");
        __syncthreads();
        if (kt + 2 < KT) LOAD_STAGE((kt + 2) % 3, kt + 2);
        asm volatile("cp.async.commit_group;");

        const bf16* sAh = smem + (kt % 3) * (GSTAGE_B / 2);
        const bf16* sAl = sAh + (GPLANE_B / 2);
        const bf16* sBh = sAh + 2 * (GPLANE_B / 2);
        const bf16* sBl = sAh + 3 * (GPLANE_B / 2);

        uint32_t Ahf[4][4], Alf[4][4];
#pragma unroll
        for (int mi = 0; mi < 4; mi++) {
            int r0 = wm * 64 + mi * 16 + g, r1 = r0 + 8;
            Ahf[mi][0] = *(const uint32_t*)(sAh + r0 * 24 + 2 * t);
            Ahf[mi][1] = *(const uint32_t*)(sAh + r1 * 24 + 2 * t);
            Ahf[mi][2] = *(const uint32_t*)(sAh + r0 * 24 + 2 * t + 8);
            Ahf[mi][3] = *(const uint32_t*)(sAh + r1 * 24 + 2 * t + 8);
            Alf[mi][0] = *(const uint32_t*)(sAl + r0 * 24 + 2 * t);
            Alf[mi][1] = *(const uint32_t*)(sAl + r1 * 24 + 2 * t);
            Alf[mi][2] = *(const uint32_t*)(sAl + r0 * 24 + 2 * t + 8);
            Alf[mi][3] = *(const uint32_t*)(sAl + r1 * 24 + 2 * t + 8);
        }
#pragma unroll
        for (int ni = 0; ni < 4; ni++) {
            int n = wn * 32 + ni * 8 + g;
            uint32_t bh0 = *(const uint32_t*)(sBh + n * 24 + 2 * t);
            uint32_t bh1 = *(const uint32_t*)(sBh + n * 24 + 2 * t + 8);
            uint32_t bl0 = *(const uint32_t*)(sBl + n * 24 + 2 * t);
            uint32_t bl1 = *(const uint32_t*)(sBl + n * 24 + 2 * t + 8);
#pragma unroll
            for (int mi = 0; mi < 4; mi++) {
                MMA_BF16(acc[mi][ni], Ahf[mi], bh0, bh1);
                MMA_BF16(acc[mi][ni], Alf[mi], bh0, bh1);
                MMA_BF16(acc[mi][ni], Ahf[mi], bl0, bl1);
            }
        }
    }
#undef LOAD_STAGE

    // epilogue
#pragma unroll
    for (int ni = 0; ni < 4; ni++) {
        const int cb = colBase + wn * 32 + ni * 8 + 2 * t;
        float b0 = 0.0f, b1 = 0.0f;
        if (BIAS) { b0 = bias[cb]; b1 = bias[cb + 1]; }
#pragma unroll
        for (int mi = 0; mi < 4; mi++) {
#pragma unroll
            for (int hh = 0; hh < 2; hh++) {
                const int rr = rowBase + wm * 64 + mi * 16 + g + hh * 8;
                float v0 = acc[mi][ni][hh * 2 + 0];
                float v1 = acc[mi][ni][hh * 2 + 1];
                if (BIAS) { v0 += b0; v1 += b1; }
                if (RELU) { v0 = fmaxf(v0, 0.0f); v1 = fmaxf(v1, 0.0f); }
                if (RES) {
                    const float2 rv = *(const float2*)&resid[(size_t)rr * N + cb];
                    v0 += rv.x; v1 += rv.y;
                }
                if (WF32) {
                    float2 ov; ov.x = v0; ov.y = v1;
                    *(float2*)&Cf[(size_t)rr * N + cb] = ov;
                }
                if (WBF) {
                    bf16 h0, l0, h1, l1;
                    split2(v0, h0, l0); split2(v1, h1, l1);
                    __nv_bfloat162 ph; ph.x = h0; ph.y = h1;
                    __nv_bfloat162 pl; pl.x = l0; pl.y = l1;
                    *(__nv_bfloat162*)&Ch[(size_t)rr * N + cb] = ph;
                    *(__nv_bfloat162*)&Cl[(size_t)rr * N + cb] = pl;
                }
            }
        }
    }
}

// ---------------- launcher ----------------
extern "C" void kernel_launch(void* const* d_in, const int* in_sizes, int n_in,
                              void* d_out, int out_size)
{
    (void)in_sizes; (void)n_in; (void)out_size;
    const int*   tokens  = (const int*)  d_in[0];
    const float* emb     = (const float*)d_in[1];
    const float* pos     = (const float*)d_in[2];
    const float* Wq      = (const float*)d_in[3];
    const float* Wk      = (const float*)d_in[4];
    const float* Wv      = (const float*)d_in[5];
    const float* Wo      = (const float*)d_in[6];
    const float* W1      = (const float*)d_in[7];
    const float* b1      = (const float*)d_in[8];
    const float* W2      = (const float*)d_in[9];
    const float* b2      = (const float*)d_in[10];
    const float* unembed = (const float*)d_in[11];
    float* out = (float*)d_out;

    bf16 *Wqkvh, *Wqkvl, *Woh, *Wol, *W1h, *W1l, *W2h, *W2l, *Ueh, *Uel;
    float *X, *X2, *QKV;
    bf16 *Xh, *Xl, *X2h, *X2l, *Oh, *Ol, *H1h, *H1l;
    cudaGetSymbolAddress((void**)&Wqkvh, g_Wqkv_h);
    cudaGetSymbolAddress((void**)&Wqkvl, g_Wqkv_l);
    cudaGetSymbolAddress((void**)&Woh,   g_Wo_h);
    cudaGetSymbolAddress((void**)&Wol,   g_Wo_l);
    cudaGetSymbolAddress((void**)&W1h,   g_W1_h);
    cudaGetSymbolAddress((void**)&W1l,   g_W1_l);
    cudaGetSymbolAddress((void**)&W2h,   g_W2_h);
    cudaGetSymbolAddress((void**)&W2l,   g_W2_l);
    cudaGetSymbolAddress((void**)&Ueh,   g_Ue_h);
    cudaGetSymbolAddress((void**)&Uel,   g_Ue_l);
    cudaGetSymbolAddress((void**)&X,   g_X);
    cudaGetSymbolAddress((void**)&X2,  g_X2);
    cudaGetSymbolAddress((void**)&Xh,  g_Xh);
    cudaGetSymbolAddress((void**)&Xl,  g_Xl);
    cudaGetSymbolAddress((void**)&X2h, g_X2h);
    cudaGetSymbolAddress((void**)&X2l, g_X2l);
    cudaGetSymbolAddress((void**)&QKV, g_QKV);
    cudaGetSymbolAddress((void**)&Oh,  g_Oh);
    cudaGetSymbolAddress((void**)&Ol,  g_Ol);
    cudaGetSymbolAddress((void**)&H1h, g_H1h);
    cudaGetSymbolAddress((void**)&H1l, g_H1l);

    const int SMEM = 3 * GSTAGE_B;
    cudaFuncSetAttribute(gemm3_kernel<false, false, false, true,  false>,
                         cudaFuncAttributeMaxDynamicSharedMemorySize, SMEM);
    cudaFuncSetAttribute(gemm3_kernel<false, false, true,  true,  true >,
                         cudaFuncAttributeMaxDynamicSharedMemorySize, SMEM);
    cudaFuncSetAttribute(gemm3_kernel<true,  true,  false, false, true >,
                         cudaFuncAttributeMaxDynamicSharedMemorySize, SMEM);
    cudaFuncSetAttribute(gemm3_kernel<true,  true,  true,  true,  true >,
                         cudaFuncAttributeMaxDynamicSharedMemorySize, SMEM);

    // ---- weight prep (transpose + bf16 split) ----
    {
        dim3 b(32, 8);
        tconv_qkv_kernel<<<dim3(2, 32, NLAYER * 48), b>>>(Wq, Wk, Wv, Wqkvh, Wqkvl);
        tconv_kernel<<<dim3(32, 32, NLAYER), b>>>(Wo, Woh, Wol, EDIM, EDIM);
        tconv_kernel<<<dim3(128, 32, NLAYER), b>>>(W1, W1h, W1l, EDIM, HID);
        tconv_kernel<<<dim3(32, 128, NLAYER), b>>>(W2, W2h, W2l, HID, EDIM);
        tconv_kernel<<<dim3(1000, 32, 1), b>>>(unembed, Ueh, Uel, EDIM, VOC);
    }

    embed_kernel<<<(NTOK * EDIM / 4) / 256, 256>>>(tokens, emb, pos, X, Xh, Xl);

    const dim3 blk(256);
    for (int l = 0; l < NLAYER; l++) {
        const bf16* wqh = Wqkvh + (size_t)l * QKVN * EDIM;
        const bf16* wql = Wqkvl + (size_t)l * QKVN * EDIM;
        const bf16* woh = Woh + (size_t)l * EDIM * EDIM;
        const bf16* wol = Wol + (size_t)l * EDIM * EDIM;
        const bf16* w1h = W1h + (size_t)l * HID * EDIM;
        const bf16* w1l = W1l + (size_t)l * HID * EDIM;
        const bf16* w2h = W2h + (size_t)l * EDIM * HID;
        const bf16* w2l = W2l + (size_t)l * EDIM * HID;
        const float* b1l = b1 + (size_t)l * HID;
        const float* b2l = b2 + (size_t)l * EDIM;

        // QKV = X @ Wqkv            [4096, 3072]
        gemm3_kernel<false, false, false, true, false>
            <<<dim3(QKVN / 128, NTOK / 128), blk, SMEM>>>(
            Xh, Xl, EDIM, wqh, wql, nullptr, nullptr, QKV, nullptr, nullptr, QKVN, EDIM);

        attn_kernel<<<BATCH * NHEAD, 64>>>(QKV, Oh, Ol);

        // X2 = O @ Wo + X           [4096, 1024]  (+ split planes)
        gemm3_kernel<false, false, true, true, true>
            <<<dim3(EDIM / 128, NTOK / 128), blk, SMEM>>>(
            Oh, Ol, EDIM, woh, wol, nullptr, X, X2, X2h, X2l, EDIM, EDIM);

        // H1 = relu(X2 @ W1 + b1)   [4096, 4096]  (split planes only)
        gemm3_kernel<true, true, false, false, true>
            <<<dim3(HID / 128, NTOK / 128), blk, SMEM>>>(
            X2h, X2l, EDIM, w1h, w1l, b1l, nullptr, nullptr, H1h, H1l, HID, EDIM);

        // X = relu(H1 @ W2 + b2) + X2   [4096, 1024]  (+ split planes)
        gemm3_kernel<true, true, true, true, true>
            <<<dim3(EDIM / 128, NTOK / 128), blk, SMEM>>>(
            H1h, H1l, HID, w2h, w2l, b2l, X2, X, Xh, Xl, EDIM, HID);
    }

    // logits = X[:, odd rows, :] @ unembed    [2048, 32000]
    gemm3_kernel<false, false, false, true, false>
        <<<dim3(VOC / 128, BATCH / 128), blk, SMEM>>>(
        Xh + EDIM, Xl + EDIM, 2 * EDIM, Ueh, Uel, nullptr, nullptr, out, nullptr, nullptr,
        VOC, EDIM);
}

// round 4
// speedup vs baseline: 2.6422x; 1.2030x over previous
#include <cuda_runtime.h>
#include <cuda_bf16.h>
#include <cstdint>
#include <math.h>

#define NTOK 4096
#define EDIM 1024
#define HID  4096
#define NLAYER 12
#define NHEAD 16
#define HDIM 64
#define BATCH 2048
#define VOC  32000
#define QKVN 3072

typedef __nv_bfloat16 bf16;

// ---------------- scratch (device globals) ----------------
__device__ bf16 g_Wqkv_h[NLAYER * QKVN * EDIM];
__device__ bf16 g_Wqkv_l[NLAYER * QKVN * EDIM];
__device__ bf16 g_Wo_h [NLAYER * EDIM * EDIM];
__device__ bf16 g_Wo_l [NLAYER * EDIM * EDIM];
__device__ bf16 g_W1_h [NLAYER * HID * EDIM];
__device__ bf16 g_W1_l [NLAYER * HID * EDIM];
__device__ bf16 g_W2_h [NLAYER * EDIM * HID];
__device__ bf16 g_W2_l [NLAYER * EDIM * HID];
__device__ bf16 g_Ue_h [VOC * EDIM];
__device__ bf16 g_Ue_l [VOC * EDIM];
__device__ float g_X  [NTOK * EDIM];
__device__ float g_X2 [NTOK * EDIM];
__device__ bf16  g_Xh [NTOK * EDIM];
__device__ bf16  g_Xl [NTOK * EDIM];
__device__ bf16  g_X2h[NTOK * EDIM];
__device__ bf16  g_X2l[NTOK * EDIM];
__device__ float g_QKV[NTOK * QKVN];
__device__ bf16  g_Oh [NTOK * EDIM];
__device__ bf16  g_Ol [NTOK * EDIM];
__device__ bf16  g_H1h[NTOK * HID];
__device__ bf16  g_H1l[NTOK * HID];

__device__ __forceinline__ void split2(float v, bf16& h, bf16& l) {
    h = __float2bfloat16(v);
    l = __float2bfloat16(v - __bfloat162float(h));
}

// ---------------- weight transpose + split ----------------
__global__ void tconv_kernel(const float* __restrict__ src,
                             bf16* __restrict__ dhi, bf16* __restrict__ dlo,
                             int K, int N)
{
    __shared__ float t[32][33];
    const int z = blockIdx.z;
    src += (size_t)z * K * N;
    dhi += (size_t)z * K * N;
    dlo += (size_t)z * K * N;
    const int k0 = blockIdx.y * 32, n0 = blockIdx.x * 32;
    const int tx = threadIdx.x, ty = threadIdx.y;
#pragma unroll
    for (int j = 0; j < 4; j++)
        t[ty + 8 * j][tx] = src[(size_t)(k0 + ty + 8 * j) * N + n0 + tx];
    __syncthreads();
#pragma unroll
    for (int j = 0; j < 4; j++) {
        float v = t[tx][ty + 8 * j];
        bf16 h, l; split2(v, h, l);
        size_t o = (size_t)(n0 + ty + 8 * j) * K + k0 + tx;
        dhi[o] = h; dlo[o] = l;
    }
}

__global__ void tconv_qkv_kernel(const float* __restrict__ Wq,
                                 const float* __restrict__ Wk,
                                 const float* __restrict__ Wv,
                                 bf16* __restrict__ dhi, bf16* __restrict__ dlo)
{
    __shared__ float t[32][33];
    const int z = blockIdx.z;
    const int l = z / 48;
    const int rr = z % 48;
    const int which = rr / 16;
    const int h = rr % 16;
    const float* src = (which == 0 ? Wq : which == 1 ? Wk : Wv)
                       + ((size_t)(l * NHEAD + h) * EDIM) * HDIM;
    const int i0 = blockIdx.x * 32;
    const int k0 = blockIdx.y * 32;
    const int tx = threadIdx.x, ty = threadIdx.y;
#pragma unroll
    for (int j = 0; j < 4; j++)
        t[ty + 8 * j][tx] = src[(size_t)(k0 + ty + 8 * j) * HDIM + i0 + tx];
    __syncthreads();
    bf16* bh = dhi + (size_t)l * QKVN * EDIM;
    bf16* bl = dlo + (size_t)l * QKVN * EDIM;
#pragma unroll
    for (int j = 0; j < 4; j++) {
        float v = t[tx][ty + 8 * j];
        bf16 hh, ll; split2(v, hh, ll);
        int n = which * 1024 + h * 64 + i0 + ty + 8 * j;
        size_t o = (size_t)n * EDIM + k0 + tx;
        bh[o] = hh; bl[o] = ll;
    }
}

// ---------------- embedding ----------------
__global__ void embed_kernel(const int* __restrict__ tokens,
                             const float* __restrict__ emb,
                             const float* __restrict__ pos,
                             float* __restrict__ X,
                             bf16* __restrict__ Xh, bf16* __restrict__ Xl)
{
    int idx = blockIdx.x * blockDim.x + threadIdx.x;
    int i  = idx / (EDIM / 4);
    int e4 = idx % (EDIM / 4);
    int tok = tokens[i];
    float4 a = ((const float4*)(emb + (size_t)tok * EDIM))[e4];
    float4 p = ((const float4*)(pos + (size_t)(i & 1) * EDIM))[e4];
    float r[4] = { a.x + p.x, a.y + p.y, a.z + p.z, a.w + p.w };
    float4 rf; rf.x = r[0]; rf.y = r[1]; rf.z = r[2]; rf.w = r[3];
    ((float4*)(X + (size_t)i * EDIM))[e4] = rf;
    bf16 hh[4], ll[4];
#pragma unroll
    for (int j = 0; j < 4; j++) split2(r[j], hh[j], ll[j]);
    size_t o = (size_t)i * EDIM + e4 * 4;
#pragma unroll
    for (int j = 0; j < 4; j++) { Xh[o + j] = hh[j]; Xl[o + j] = ll[j]; }
}

// ---------------- attention (T=2) ----------------
__global__ void attn_kernel(const float* __restrict__ QKV,
                            bf16* __restrict__ Oh, bf16* __restrict__ Ol)
{
    const int bh = blockIdx.x;
    const int b = bh >> 4;
    const int h = bh & 15;
    const int o = threadIdx.x;
    const size_t q0i = (size_t)(b * 2) * QKVN + h * HDIM + o;
    const size_t q1i = q0i + QKVN;

    float q0 = QKV[q0i],        q1 = QKV[q1i];
    float k0 = QKV[q0i + 1024], k1 = QKV[q1i + 1024];
    float v0 = QKV[q0i + 2048], v1 = QKV[q1i + 2048];

    float d00 = q0 * k0, d01 = q0 * k1, d10 = q1 * k0, d11 = q1 * k1;
    const unsigned mask = 0xffffffffu;
#pragma unroll
    for (int off = 16; off; off >>= 1) {
        d00 += __shfl_down_sync(mask, d00, off);
        d01 += __shfl_down_sync(mask, d01, off);
        d10 += __shfl_down_sync(mask, d10, off);
        d11 += __shfl_down_sync(mask, d11, off);
    }
    __shared__ float part[4][2];
    __shared__ float p[4];
    const int warp = o >> 5;
    if ((o & 31) == 0) {
        part[0][warp] = d00; part[1][warp] = d01;
        part[2][warp] = d10; part[3][warp] = d11;
    }
    __syncthreads();
    if (o == 0) {
        const float scale = 0.125f;
        float s00 = (part[0][0] + part[0][1]) * scale;
        float s01 = (part[1][0] + part[1][1]) * scale;
        float s10 = (part[2][0] + part[2][1]) * scale;
        float s11 = (part[3][0] + part[3][1]) * scale;
        float m0 = fmaxf(s00, s01);
        float e00 = expf(s00 - m0), e01 = expf(s01 - m0);
        float i0 = 1.0f / (e00 + e01);
        float m1 = fmaxf(s10, s11);
        float e10 = expf(s10 - m1), e11 = expf(s11 - m1);
        float i1 = 1.0f / (e10 + e11);
        p[0] = e00 * i0; p[1] = e01 * i0; p[2] = e10 * i1; p[3] = e11 * i1;
    }
    __syncthreads();
    const size_t o0 = (size_t)(b * 2) * EDIM + h * HDIM + o;
    bf16 hh, ll;
    split2(p[0] * v0 + p[1] * v1, hh, ll); Oh[o0] = hh;        Ol[o0] = ll;
    split2(p[2] * v0 + p[3] * v1, hh, ll); Oh[o0 + EDIM] = hh; Ol[o0 + EDIM] = ll;
}

// ---------------- 3xBF16 tensor-core GEMM (mma.sync, term-major) ----------------
#define MMA_BF16(d, a, b0, b1)                                             \
    asm volatile("mma.sync.aligned.m16n8k16.row.col.f32.bf16.bf16.f32 "    \
                 "{%0,%1,%2,%3},{%4,%5,%6,%7},{%8,%9},{%0,%1,%2,%3};"      \
                 : "+f"(d[0]), "+f"(d[1]), "+f"(d[2]), "+f"(d[3])          \
                 : "r"(a[0]), "r"(a[1]), "r"(a[2]), "r"(a[3]),             \
                   "r"(b0), "r"(b1))

#define LDSM_X4(r, a)                                                       \
    asm volatile("ldmatrix.sync.aligned.m8n8.x4.shared.b16 {%0,%1,%2,%3}, [%4];" \
                 : "=r"((r)[0]), "=r"((r)[1]), "=r"((r)[2]), "=r"((r)[3])   \
                 : "r"(a))

__device__ __forceinline__ void cpa16(uint32_t dst, const void* src) {
    asm volatile("cp.async.cg.shared.global [%0], [%1], 16;\n" :: "r"(dst), "l"(src));
}

// smem per stage: aH[128*24] aL bH bL (bf16), row stride 24 halves.
#define GSTAGE_B 24576
#define GPLANE_B 6144

template<bool BIAS, bool RELU, bool RES, bool WF32, bool WBF>
__global__ void __launch_bounds__(256, 2)
gemm3_kernel(const bf16* __restrict__ Ah_, const bf16* __restrict__ Al_, int lda,
             const bf16* __restrict__ Bh_, const bf16* __restrict__ Bl_,
             const float* __restrict__ bias, const float* __restrict__ resid,
             float* __restrict__ Cf, bf16* __restrict__ Ch, bf16* __restrict__ Cl,
             int N, int K)
{
    extern __shared__ bf16 smem[];
    const int tid  = threadIdx.x;
    const int lane = tid & 31, warp = tid >> 5;
    const int wm = warp >> 2, wn = warp & 3;       // 2x4 warp grid, warp tile 64x32
    const int g = lane >> 2, t = lane & 3;
    const int rowBase = blockIdx.y * 128;
    const int colBase = blockIdx.x * 128;

    // global loaders
    const int lr = tid >> 1;
    const int lc = (tid & 1) * 8;
    const bf16* gAh = Ah_ + (size_t)(rowBase + lr) * lda + lc;
    const bf16* gAl = Al_ + (size_t)(rowBase + lr) * lda + lc;
    const bf16* gBh = Bh_ + (size_t)(colBase + lr) * K + lc;
    const bf16* gBl = Bl_ + (size_t)(colBase + lr) * K + lc;
    const uint32_t sbase = (uint32_t)__cvta_generic_to_shared(smem);
    const uint32_t sw = sbase + (lr * 24 + lc) * 2;

#define LOAD_STAGE(S, KT)                                       \
    do {                                                        \
        uint32_t b_ = sw + (S) * GSTAGE_B;                      \
        int ko_ = (KT) * 16;                                    \
        cpa16(b_,                gAh + ko_);                    \
        cpa16(b_ + GPLANE_B,     gAl + ko_);                    \
        cpa16(b_ + 2 * GPLANE_B, gBh + ko_);                    \
        cpa16(b_ + 3 * GPLANE_B, gBl + ko_);                    \
    } while (0)

    // ldmatrix per-lane offsets (bytes)
    const int lq  = lane & 7;
    const int l8  = (lane >> 3) & 1;
    const int l16 = (lane >> 4) & 1;
    uint32_t offA[4], offB[2];
#pragma unroll
    for (int mi = 0; mi < 4; mi++)
        offA[mi] = ((wm * 64 + mi * 16 + lq + 8 * l8) * 24 + 8 * l16) * 2;
#pragma unroll
    for (int pi = 0; pi < 2; pi++)
        offB[pi] = ((wn * 32 + pi * 16 + lq + 8 * l16) * 24 + 8 * l8) * 2;

    float acc[4][4][4];
#pragma unroll
    for (int i = 0; i < 4; i++)
#pragma unroll
        for (int j = 0; j < 4; j++)
#pragma unroll
            for (int q = 0; q < 4; q++) acc[i][j][q] = 0.0f;

    const int KT = K >> 4;
    LOAD_STAGE(0, 0); asm volatile("cp.async.commit_group;");
    LOAD_STAGE(1, 1); asm volatile("cp.async.commit_group;");

    for (int kt = 0; kt < KT; ++kt) {
        asm volatile("cp.async.wait_group 1;" ::: "memory");
        __syncthreads();
        if (kt + 2 < KT) LOAD_STAGE((kt + 2) % 3, kt + 2);
        asm volatile("cp.async.commit_group;");

        const uint32_t st = sbase + (kt % 3) * GSTAGE_B;
        const uint32_t aH = st;
        const uint32_t aL = st + GPLANE_B;
        const uint32_t bH = st + 2 * GPLANE_B;
        const uint32_t bL = st + 3 * GPLANE_B;

        uint32_t a[4][4];       // Ah, later reused for Al
        uint32_t bh[4][2], bl[4][2];
#pragma unroll
        for (int mi = 0; mi < 4; mi++) LDSM_X4(a[mi], aH + offA[mi]);
#pragma unroll
        for (int pi = 0; pi < 2; pi++) {
            uint32_t r4[4];
            LDSM_X4(r4, bH + offB[pi]);
            bh[2 * pi][0] = r4[0]; bh[2 * pi][1] = r4[1];
            bh[2 * pi + 1][0] = r4[2]; bh[2 * pi + 1][1] = r4[3];
            LDSM_X4(r4, bL + offB[pi]);
            bl[2 * pi][0] = r4[0]; bl[2 * pi][1] = r4[1];
            bl[2 * pi + 1][0] = r4[2]; bl[2 * pi + 1][1] = r4[3];
        }

        // term 1: Ah * Bh   (16 independent MMAs)
#pragma unroll
        for (int ni = 0; ni < 4; ni++)
#pragma unroll
            for (int mi = 0; mi < 4; mi++)
                MMA_BF16(acc[mi][ni], a[mi], bh[ni][0], bh[ni][1]);
        // term 2: Ah * Bl
#pragma unroll
        for (int ni = 0; ni < 4; ni++)
#pragma unroll
            for (int mi = 0; mi < 4; mi++)
                MMA_BF16(acc[mi][ni], a[mi], bl[ni][0], bl[ni][1]);
        // reload A as lo plane
#pragma unroll
        for (int mi = 0; mi < 4; mi++) LDSM_X4(a[mi], aL + offA[mi]);
        // term 3: Al * Bh
#pragma unroll
        for (int ni = 0; ni < 4; ni++)
#pragma unroll
            for (int mi = 0; mi < 4; mi++)
                MMA_BF16(acc[mi][ni], a[mi], bh[ni][0], bh[ni][1]);
    }
#undef LOAD_STAGE

    // epilogue
#pragma unroll
    for (int ni = 0; ni < 4; ni++) {
        const int cb = colBase + wn * 32 + ni * 8 + 2 * t;
        float b0 = 0.0f, b1 = 0.0f;
        if (BIAS) { b0 = bias[cb]; b1 = bias[cb + 1]; }
#pragma unroll
        for (int mi = 0; mi < 4; mi++) {
#pragma unroll
            for (int hh = 0; hh < 2; hh++) {
                const int rr = rowBase + wm * 64 + mi * 16 + g + hh * 8;
                float v0 = acc[mi][ni][hh * 2 + 0];
                float v1 = acc[mi][ni][hh * 2 + 1];
                if (BIAS) { v0 += b0; v1 += b1; }
                if (RELU) { v0 = fmaxf(v0, 0.0f); v1 = fmaxf(v1, 0.0f); }
                if (RES) {
                    const float2 rv = *(const float2*)&resid[(size_t)rr * N + cb];
                    v0 += rv.x; v1 += rv.y;
                }
                if (WF32) {
                    float2 ov; ov.x = v0; ov.y = v1;
                    *(float2*)&Cf[(size_t)rr * N + cb] = ov;
                }
                if (WBF) {
                    bf16 h0, l0, h1, l1;
                    split2(v0, h0, l0); split2(v1, h1, l1);
                    __nv_bfloat162 ph; ph.x = h0; ph.y = h1;
                    __nv_bfloat162 pl; pl.x = l0; pl.y = l1;
                    *(__nv_bfloat162*)&Ch[(size_t)rr * N + cb] = ph;
                    *(__nv_bfloat162*)&Cl[(size_t)rr * N + cb] = pl;
                }
            }
        }
    }
}

// ---------------- launcher ----------------
extern "C" void kernel_launch(void* const* d_in, const int* in_sizes, int n_in,
                              void* d_out, int out_size)
{
    (void)in_sizes; (void)n_in; (void)out_size;
    const int*   tokens  = (const int*)  d_in[0];
    const float* emb     = (const float*)d_in[1];
    const float* pos     = (const float*)d_in[2];
    const float* Wq      = (const float*)d_in[3];
    const float* Wk      = (const float*)d_in[4];
    const float* Wv      = (const float*)d_in[5];
    const float* Wo      = (const float*)d_in[6];
    const float* W1      = (const float*)d_in[7];
    const float* b1      = (const float*)d_in[8];
    const float* W2      = (const float*)d_in[9];
    const float* b2      = (const float*)d_in[10];
    const float* unembed = (const float*)d_in[11];
    float* out = (float*)d_out;

    bf16 *Wqkvh, *Wqkvl, *Woh, *Wol, *W1h, *W1l, *W2h, *W2l, *Ueh, *Uel;
    float *X, *X2, *QKV;
    bf16 *Xh, *Xl, *X2h, *X2l, *Oh, *Ol, *H1h, *H1l;
    cudaGetSymbolAddress((void**)&Wqkvh, g_Wqkv_h);
    cudaGetSymbolAddress((void**)&Wqkvl, g_Wqkv_l);
    cudaGetSymbolAddress((void**)&Woh,   g_Wo_h);
    cudaGetSymbolAddress((void**)&Wol,   g_Wo_l);
    cudaGetSymbolAddress((void**)&W1h,   g_W1_h);
    cudaGetSymbolAddress((void**)&W1l,   g_W1_l);
    cudaGetSymbolAddress((void**)&W2h,   g_W2_h);
    cudaGetSymbolAddress((void**)&W2l,   g_W2_l);
    cudaGetSymbolAddress((void**)&Ueh,   g_Ue_h);
    cudaGetSymbolAddress((void**)&Uel,   g_Ue_l);
    cudaGetSymbolAddress((void**)&X,   g_X);
    cudaGetSymbolAddress((void**)&X2,  g_X2);
    cudaGetSymbolAddress((void**)&Xh,  g_Xh);
    cudaGetSymbolAddress((void**)&Xl,  g_Xl);
    cudaGetSymbolAddress((void**)&X2h, g_X2h);
    cudaGetSymbolAddress((void**)&X2l, g_X2l);
    cudaGetSymbolAddress((void**)&QKV, g_QKV);
    cudaGetSymbolAddress((void**)&Oh,  g_Oh);
    cudaGetSymbolAddress((void**)&Ol,  g_Ol);
    cudaGetSymbolAddress((void**)&H1h, g_H1h);
    cudaGetSymbolAddress((void**)&H1l, g_H1l);

    const int SMEM = 3 * GSTAGE_B;
    cudaFuncSetAttribute(gemm3_kernel<false, false, false, true,  false>,
                         cudaFuncAttributeMaxDynamicSharedMemorySize, SMEM);
    cudaFuncSetAttribute(gemm3_kernel<false, false, true,  true,  true >,
                         cudaFuncAttributeMaxDynamicSharedMemorySize, SMEM);
    cudaFuncSetAttribute(gemm3_kernel<true,  true,  false, false, true >,
                         cudaFuncAttributeMaxDynamicSharedMemorySize, SMEM);
    cudaFuncSetAttribute(gemm3_kernel<true,  true,  true,  true,  true >,
                         cudaFuncAttributeMaxDynamicSharedMemorySize, SMEM);

    // ---- weight prep (transpose + bf16 split) ----
    {
        dim3 b(32, 8);
        tconv_qkv_kernel<<<dim3(2, 32, NLAYER * 48), b>>>(Wq, Wk, Wv, Wqkvh, Wqkvl);
        tconv_kernel<<<dim3(32, 32, NLAYER), b>>>(Wo, Woh, Wol, EDIM, EDIM);
        tconv_kernel<<<dim3(128, 32, NLAYER), b>>>(W1, W1h, W1l, EDIM, HID);
        tconv_kernel<<<dim3(32, 128, NLAYER), b>>>(W2, W2h, W2l, HID, EDIM);
        tconv_kernel<<<dim3(1000, 32, 1), b>>>(unembed, Ueh, Uel, EDIM, VOC);
    }

    embed_kernel<<<(NTOK * EDIM / 4) / 256, 256>>>(tokens, emb, pos, X, Xh, Xl);

    const dim3 blk(256);
    for (int l = 0; l < NLAYER; l++) {
        const bf16* wqh = Wqkvh + (size_t)l * QKVN * EDIM;
        const bf16* wql = Wqkvl + (size_t)l * QKVN * EDIM;
        const bf16* woh = Woh + (size_t)l * EDIM * EDIM;
        const bf16* wol = Wol + (size_t)l * EDIM * EDIM;
        const bf16* w1h = W1h + (size_t)l * HID * EDIM;
        const bf16* w1l = W1l + (size_t)l * HID * EDIM;
        const bf16* w2h = W2h + (size_t)l * EDIM * HID;
        const bf16* w2l = W2l + (size_t)l * EDIM * HID;
        const float* b1l = b1 + (size_t)l * HID;
        const float* b2l = b2 + (size_t)l * EDIM;

        // QKV = X @ Wqkv            [4096, 3072]
        gemm3_kernel<false, false, false, true, false>
            <<<dim3(QKVN / 128, NTOK / 128), blk, SMEM>>>(
            Xh, Xl, EDIM, wqh, wql, nullptr, nullptr, QKV, nullptr, nullptr, QKVN, EDIM);

        attn_kernel<<<BATCH * NHEAD, 64>>>(QKV, Oh, Ol);

        // X2 = O @ Wo + X           [4096, 1024]  (+ split planes)
        gemm3_kernel<false, false, true, true, true>
            <<<dim3(EDIM / 128, NTOK / 128), blk, SMEM>>>(
            Oh, Ol, EDIM, woh, wol, nullptr, X, X2, X2h, X2l, EDIM, EDIM);

        // H1 = relu(X2 @ W1 + b1)   [4096, 4096]  (split planes only)
        gemm3_kernel<true, true, false, false, true>
            <<<dim3(HID / 128, NTOK / 128), blk, SMEM>>>(
            X2h, X2l, EDIM, w1h, w1l, b1l, nullptr, nullptr, H1h, H1l, HID, EDIM);

        // X = relu(H1 @ W2 + b2) + X2   [4096, 1024]  (+ split planes)
        gemm3_kernel<true, true, true, true, true>
            <<<dim3(EDIM / 128, NTOK / 128), blk, SMEM>>>(
            H1h, H1l, HID, w2h, w2l, b2l, X2, X, Xh, Xl, EDIM, HID);
    }

    // logits = X[:, odd rows, :] @ unembed    [2048, 32000]
    gemm3_kernel<false, false, false, true, false>
        <<<dim3(VOC / 128, BATCH / 128), blk, SMEM>>>(
        Xh + EDIM, Xl + EDIM, 2 * EDIM, Ueh, Uel, nullptr, nullptr, out, nullptr, nullptr,
        VOC, EDIM);
}